// round 14
// baseline (speedup 1.0000x reference)
#include <cuda_runtime.h>
#include <math.h>

#define TPB 256
#define TS 16
#define MAXN 1024
#define NT1 4096
#define NT2 1024
#define Y1MAX 6.08f
#define MAXT 16
#define NK_HALF 2456
#define NB_RECIP 307   // 307*8 = 2456 warps, one per half-space k
#define FULLMASK 0xffffffffu

__device__ float2 g_T1[NT1];            // erfc(y), y in [0, Y1MAX]
__device__ float2 g_T2[NT2];            // erfc(r*inve)/r by r^2 in [0,cutr2]
__device__ float  g_igs[MAXT * MAXT];   // invgamma * scale1 per species pair
__device__ float  g_gg[MAXT * MAXT];    // r2 threshold under which gamma matters
__device__ float2 g_phx[9 * MAXN];      // q * e^{i m u}
__device__ float2 g_phy[9 * MAXN];      //     e^{i m v}
__device__ float2 g_phz[9 * MAXN];      //     e^{i m w}

struct AccT {
    double r[32];
    double k[32];
    unsigned int cnt;
    unsigned int pad[31];
};
__device__ AccT g_acc;   // zero at load; self-resetting per run

__device__ __forceinline__ float blockReduceF(float v) {
    __shared__ float sh[32];
    int lane = threadIdx.x & 31, w = threadIdx.x >> 5;
    #pragma unroll
    for (int o = 16; o; o >>= 1) v += __shfl_down_sync(FULLMASK, v, o);
    if (lane == 0) sh[w] = v;
    __syncthreads();
    if (w == 0) {
        v = (lane < (TPB >> 5)) ? sh[lane] : 0.f;
        #pragma unroll
        for (int o = 16; o; o >>= 1) v += __shfl_down_sync(FULLMASK, v, o);
    }
    return v;
}

__device__ __forceinline__ float fast_eta(float vol, int n) {
    return __expf(__logf(vol * vol / (float)n) * 0.16666667f) * 0.39894228040143267f;
}

// AS 7.1.26 erfc (slow/rare paths only)
__device__ __forceinline__ float erfc_as(float x) {
    float t = __fdividef(1.0f, fmaf(0.3275911f, x, 1.0f));
    float p = t * fmaf(t, fmaf(t, fmaf(t, fmaf(t, 1.061405429f, -1.453152027f),
              1.421413741f), -0.284496736f), 0.254829592f);
    return p * __expf(-x * x);
}

// linear interp, global table (L1/L2 cached), pre-scaled index
__device__ __forceinline__ float lutg(const float2* __restrict__ T, float x, int nmax) {
    x = fminf(fmaxf(x, 0.f), (float)(nmax - 1) - 1e-3f);
    int idx = (int)x;
    float fr = x - (float)idx;
    float2 e = __ldg(&T[idx]);
    return fmaf(fr, e.y, e.x);
}

// ---------------- setup: all tables + phase factors (once per replay) -------
__global__ void k_setup(const float* __restrict__ pos, const float* __restrict__ cell,
                        const float* __restrict__ q, const float* __restrict__ sigt,
                        int n, int ntypes) {
    float c00 = __ldg(cell + 0), c01 = __ldg(cell + 1), c02 = __ldg(cell + 2);
    float c10 = __ldg(cell + 3), c11 = __ldg(cell + 4), c12 = __ldg(cell + 5);
    float c20 = __ldg(cell + 6), c21 = __ldg(cell + 7), c22 = __ldg(cell + 8);
    float det = c00 * (c11 * c22 - c12 * c21)
              - c01 * (c10 * c22 - c12 * c20)
              + c02 * (c10 * c21 - c11 * c20);
    float vol = fabsf(det);
    float eta = fast_eta(vol, n);
    float cutr = 6.0697085114f * eta;
    float cutr2 = cutr * cutr;
    float inve = 0.7071067811865476f / eta;

    int t = blockIdx.x * blockDim.x + threadIdx.x;
    if (t < NT1) {
        float dy = Y1MAX / (float)NT1;
        float f0 = erfcf(t * dy);
        float f1 = erfcf((t + 1) * dy);
        g_T1[t] = make_float2(f0, f1 - f0);
    } else if (t < NT1 + NT2) {
        int i = t - NT1;
        float du = cutr2 / (float)NT2;
        float u0 = i * du, u1 = u0 + du;
        float f0 = 0.f, f1 = 0.f;
        if (i > 0) { float r0 = sqrtf(u0); f0 = erfcf(r0 * inve) / r0; }
        { float r1 = sqrtf(u1); f1 = erfcf(r1 * inve) / r1; }
        if (i + 1 == NT2) f1 = 0.f;
        g_T2[i] = make_float2(f0, f1 - f0);
    } else if (t < NT1 + NT2 + MAXT * MAXT) {
        int p = t - NT1 - NT2;
        int si = p / MAXT, sj = p % MAXT;
        float igs = 0.f, gg = -1.f;
        if (si < ntypes && sj < ntypes) {
            float a = __ldg(sigt + si), bsg = __ldg(sigt + sj);
            float s2 = 2.f * (a * a + bsg * bsg);
            float invg = rsqrtf(s2);
            igs = invg * ((float)NT1 / Y1MAX);
            gg = 16.5f * s2;                 // r2 below which gamma-erfc > ~1.5e-8
        }
        g_igs[p] = igs;
        g_gg[p] = gg;
    } else if (t < NT1 + NT2 + MAXT * MAXT + MAXN) {
        int a = t - NT1 - NT2 - MAXT * MAXT;
        if (a < n && a < MAXN) {
            float px = __ldg(pos + 3*a), py = __ldg(pos + 3*a + 1), pz = __ldg(pos + 3*a + 2);
            float id = 6.283185307179586f / det;
            float u = (px*(c11*c22-c12*c21) + py*(c12*c20-c10*c22) + pz*(c10*c21-c11*c20)) * id;
            float v = (px*(c02*c21-c01*c22) + py*(c00*c22-c02*c20) + pz*(c01*c20-c00*c21)) * id;
            float w = (px*(c01*c12-c02*c11) + py*(c02*c10-c00*c12) + pz*(c00*c11-c01*c10)) * id;
            float su, cu, sv, cv, sw, cw;
            sincosf(u, &su, &cu);
            sincosf(v, &sv, &cv);
            sincosf(w, &sw, &cw);
            float qa = __ldg(q + a);
            float xr = qa, xi = 0.f;
            float yr = 1.f, yi = 0.f;
            float zr = 1.f, zi = 0.f;
            #pragma unroll
            for (int m = 0; m < 9; ++m) {
                g_phx[m * MAXN + a] = make_float2(xr, xi);
                g_phy[m * MAXN + a] = make_float2(yr, yi);
                g_phz[m * MAXN + a] = make_float2(zr, zi);
                float nxr = xr * cu - xi * su; xi = xr * su + xi * cu; xr = nxr;
                float nyr = yr * cv - yi * sv; yi = yr * sv + yi * cv; yr = nyr;
                float nzr = zr * cw - zi * sw; zi = zr * sw + zi * cw; zr = nzr;
            }
        }
    }
}

__global__ void __launch_bounds__(TPB)
k_main(const float* __restrict__ pos, const float* __restrict__ cell,
       const float* __restrict__ q, const float* __restrict__ sigt,
       const int* __restrict__ spec, const int* __restrict__ nsr,
       const int* __restrict__ nkr, float* __restrict__ out,
       int n, int ntypes, unsigned int total_blocks) {
    __shared__ float4 sjt[TS]; __shared__ float4 sit[TS];
    __shared__ float  sjs2[TS]; __shared__ float sis2[TS];
    __shared__ int    sjsp[TS]; __shared__ int   sisp[TS];
    int tid = threadIdx.x;
    int b = blockIdx.x;

    float c00 = __ldg(cell + 0), c01 = __ldg(cell + 1), c02 = __ldg(cell + 2);
    float c10 = __ldg(cell + 3), c11 = __ldg(cell + 4), c12 = __ldg(cell + 5);
    float c20 = __ldg(cell + 6), c21 = __ldg(cell + 7), c22 = __ldg(cell + 8);
    float det = c00 * (c11 * c22 - c12 * c21)
              - c01 * (c10 * c22 - c12 * c20)
              + c02 * (c10 * c21 - c11 * c20);
    float vol = fabsf(det);
    float eta = fast_eta(vol, n);
    const float SQRT_2LOG = 6.0697085114f;
    float cutr = SQRT_2LOG * eta;
    float cutr2 = cutr * cutr;
    float inve = 0.7071067811865476f / eta;

    if (b < NB_RECIP) {
        // ---------- reciprocal: one warp per half-space k, phase tables ------
        int w = tid >> 5, lane = tid & 31;
        int widx = b * 8 + w;
        const float TWO_PI = 6.283185307179586f;
        float cutk2 = (SQRT_2LOG / eta) * (SQRT_2LOG / eta);
        int nk = __ldg(nkr);
        int f = 2457 + widx;
        int kx = f % 17 - 8;
        int ky = (f / 17) % 17 - 8;
        int kz = f / 289 - 8;
        if (abs(kx) <= nk && abs(ky) <= nk && abs(kz) <= nk) {
            float id = __fdividef(TWO_PI, det);
            float kax = (kx*(c11*c22-c12*c21) + ky*(c12*c20-c10*c22) + kz*(c10*c21-c11*c20)) * id;
            float kay = (kx*(c02*c21-c01*c22) + ky*(c00*c22-c02*c20) + kz*(c01*c20-c00*c21)) * id;
            float kaz = (kx*(c01*c12-c02*c11) + ky*(c02*c10-c00*c12) + kz*(c00*c11-c01*c10)) * id;
            float k2 = kax*kax + kay*kay + kaz*kaz;
            if (k2 > 1e-16f && k2 < cutk2) {
                float wgt = __fdividef(__expf(-0.5f * eta * eta * k2), k2);
                float sc = 0.f, ss = 0.f;
                if (n <= MAXN) {
                    int mx = abs(kx), my = abs(ky), mz = abs(kz);
                    float sgx = (kx < 0) ? -1.f : 1.f;
                    float sgy = (ky < 0) ? -1.f : 1.f;
                    float sgz = (kz < 0) ? -1.f : 1.f;
                    const float2* PX = g_phx + mx * MAXN;
                    const float2* PY = g_phy + my * MAXN;
                    const float2* PZ = g_phz + mz * MAXN;
                    for (int i2 = lane; i2 < n; i2 += 32) {
                        float2 X = __ldg(PX + i2);
                        float2 Y = __ldg(PY + i2);
                        float2 Z = __ldg(PZ + i2);
                        float Xi = X.y * sgx, Yi = Y.y * sgy, Zi = Z.y * sgz;
                        float tr = X.x * Y.x - Xi * Yi;
                        float ti = X.x * Yi + Xi * Y.x;
                        sc += tr * Z.x - ti * Zi;
                        ss += tr * Zi + ti * Z.x;
                    }
                } else {
                    for (int i2 = lane; i2 < n; i2 += 32) {
                        float th = fmaf(kax, __ldg(pos+3*i2),
                                   fmaf(kay, __ldg(pos+3*i2+1), kaz * __ldg(pos+3*i2+2)));
                        th -= TWO_PI * rintf(th * 0.15915494309189535f);
                        float s, c;
                        __sincosf(th, &s, &c);
                        float qv = __ldg(q + i2);
                        sc = fmaf(qv, c, sc);
                        ss = fmaf(qv, s, ss);
                    }
                }
                #pragma unroll
                for (int o = 16; o; o >>= 1) {
                    sc += __shfl_down_sync(FULLMASK, sc, o);
                    ss += __shfl_down_sync(FULLMASK, ss, o);
                }
                if (lane == 0)
                    atomicAdd(&g_acc.k[widx & 31], (double)(2.0f * wgt * (sc*sc + ss*ss)));
            }
        }
    } else {
        // ---------- real space: one block per ordered 16x16 tile pair --------
        int bt = b - NB_RECIP;
        int ti = (int)(sqrtf(2.0f * (float)bt + 0.25f) - 0.5f);
        if ((ti + 1) * (ti + 2) / 2 <= bt) ++ti;
        if (ti * (ti + 1) / 2 > bt) --ti;
        int tj = bt - ti * (ti + 1) / 2;
        bool diagT = (ti == tj);

        if (tid < TS) {
            int a = tj * TS + tid;
            float4 v = make_float4(0.f, 0.f, 0.f, 0.f);
            float s2 = 1.f; int sp = 0;
            if (a < n) {
                v = make_float4(__ldg(pos+3*a), __ldg(pos+3*a+1), __ldg(pos+3*a+2),
                                __ldg(q+a) * (diagT ? 1.0f : 2.0f));
                sp = __ldg(spec + a);
                float sg = __ldg(sigt + sp);
                s2 = 2.0f * sg * sg;
            }
            sjt[tid] = v; sjs2[tid] = s2; sjsp[tid] = sp;
        } else if (tid < 2 * TS) {
            int li = tid - TS;
            int a = ti * TS + li;
            float4 v = make_float4(0.f, 0.f, 0.f, 0.f);
            float s2 = 1.f; int sp = 0;
            if (a < n) {
                v = make_float4(__ldg(pos+3*a), __ldg(pos+3*a+1), __ldg(pos+3*a+2),
                                __ldg(q+a));
                sp = __ldg(spec + a);
                float sg = __ldg(sigt + sp);
                s2 = 2.0f * sg * sg;
            }
            sit[li] = v; sis2[li] = s2; sisp[li] = sp;
        }
        __syncthreads();

        int li = tid & (TS - 1);
        int lj = tid >> 4;
        float4 Pi = sit[li]; float4 Pj = sjt[lj];
        float qq = Pi.w * Pj.w;
        if (diagT) {
            int i = ti * TS + li, j = tj * TS + lj;
            qq *= (j < i) ? 2.0f : ((j == i) ? 1.0f : 0.0f);
        }
        float local = 0.f;

        int ns = __ldg(nsr);
        bool diag = (c01==0.f && c02==0.f && c10==0.f && c12==0.f && c20==0.f && c21==0.f);
        bool fast = diag && ns >= 1 && ntypes <= MAXT &&
                    cutr2 <= c00*c00 && cutr2 <= c11*c11 && cutr2 <= c22*c22;

        float dx = Pj.x - Pi.x, dy = Pj.y - Pi.y, dz = Pj.z - Pi.z;

        if (fast) {   // warp-uniform
            int pid = sisp[li] * MAXT + sjsp[lj];
            float igs = __ldg(&g_igs[pid]);
            float gg  = __ldg(&g_gg[pid]);
            float iLx = __fdividef(1.0f, c00);
            float iLy = __fdividef(1.0f, c11);
            float iLz = __fdividef(1.0f, c22);
            const float scale1 = (float)NT1 / Y1MAX;
            float inveS = inve * scale1;
            float scale2 = __fdividef((float)NT2, cutr2);

            float x0 = fmaf(-c00, rintf(dx * iLx), dx);
            float y0 = fmaf(-c11, rintf(dy * iLy), dy);
            float z0 = fmaf(-c22, rintf(dz * iLz), dz);
            float x1 = x0 - copysignf(c00, x0);
            float y1 = y0 - copysignf(c11, y0);
            float z1 = z0 - copysignf(c22, z0);
            float xs0 = x0*x0, xs1 = x1*x1;
            float ys0 = y0*y0, ys1 = y1*y1;
            float zs0 = z0*z0, zs1 = z1*z1;

            // min image: 1 rsqrt + 2 small-table lookups
            {
                float r2 = xs0 + ys0 + zs0;
                float rinv = rsqrtf(fmaxf(r2, 1e-12f));
                float r = r2 * rinv;
                float vA = lutg(g_T1, r * inveS, NT1);
                float vB = lutg(g_T1, r * igs, NT1);
                float okq = (r2 > 1e-16f) ? qq : 0.f;
                local = fmaf(okq, (vA - vB) * rinv, local);
            }
            // secondary images: 7 branch-free T2 lookups (zero MUFU)
            float r2c[7];
            #pragma unroll
            for (int c = 1; c < 8; ++c)
                r2c[c-1] = ((c & 1) ? xs1 : xs0) + ((c & 2) ? ys1 : ys0)
                         + ((c & 4) ? zs1 : zs0);
            float msec = r2c[0];
            #pragma unroll
            for (int c = 1; c < 7; ++c) msec = fminf(msec, r2c[c]);

            if (msec < gg) {     // gamma matters at secondary range: exact (rare)
                float invg = rsqrtf(sjs2[lj] + sis2[li]);
                #pragma unroll
                for (int c = 0; c < 7; ++c) {
                    float r2 = r2c[c];
                    if (r2 > 1e-16f && r2 < cutr2) {
                        float rinv = rsqrtf(r2);
                        float r = r2 * rinv;
                        local += qq * (erfc_as(r*inve) - erfc_as(r*invg)) * rinv;
                    }
                }
            } else {
                #pragma unroll
                for (int c = 0; c < 7; ++c)
                    local = fmaf(qq, lutg(g_T2, r2c[c] * scale2, NT2), local);
            }
        } else {
            float invg = rsqrtf(sis2[li] + sjs2[lj]);
            for (int sx = -ns; sx <= ns; ++sx)
                for (int sy = -ns; sy <= ns; ++sy) {
                    float bx = dx + sx*c00 + sy*c10;
                    float by = dy + sx*c01 + sy*c11;
                    float bz = dz + sx*c02 + sy*c12;
                    for (int sz = -ns; sz <= ns; ++sz) {
                        float ax = bx + sz*c20, ay = by + sz*c21, az = bz + sz*c22;
                        float r2 = ax*ax + ay*ay + az*az;
                        if (r2 > 1e-16f && r2 < cutr2) {
                            float rinv = rsqrtf(r2);
                            float r = r2 * rinv;
                            local += qq * (erfc_as(r*inve) - erfc_as(r*invg)) * rinv;
                        }
                    }
                }
        }
        float tot = blockReduceF(local);
        if (tid == 0) atomicAdd(&g_acc.r[b & 31], (double)tot);
    }

    // ---------------- last block: self term + combine + RESET ---------------
    __shared__ bool isLast;
    __syncthreads();
    if (tid == 0) {
        __threadfence();
        unsigned int prev = atomicAdd(&g_acc.cnt, 1u);
        isLast = (prev == total_blocks - 1);
    }
    __syncthreads();
    if (!isLast) return;

    __shared__ double shd[64];
    if (tid < 64)
        shd[tid] = (tid < 32) ? __ldcg(&g_acc.r[tid]) : __ldcg(&g_acc.k[tid - 32]);
    __syncthreads();

    if (tid < 32) { g_acc.r[tid] = 0.0; g_acc.k[tid] = 0.0; }
    if (tid == 0) g_acc.cnt = 0u;

    float a = -0.7978845608028654f / eta;
    float selfLocal = 0.f;
    for (int i2 = tid; i2 < n; i2 += TPB) {
        float qv = __ldg(q + i2);
        float sg = __ldg(sigt + __ldg(spec + i2));
        selfLocal += qv * qv * (a + 0.5641895835477563f / sg);
    }
    float selfSum = blockReduceF(selfLocal);
    if (tid == 0) {
        double sr = 0.0, sk = 0.0;
        #pragma unroll
        for (int tt = 0; tt < 32; ++tt) { sr += shd[tt]; sk += shd[32 + tt]; }
        const double COEF = 14.399645478425668;
        double E = 0.5 * COEF * (sr + (4.0 * M_PI / (double)vol) * sk + (double)selfSum);
        out[0] = (float)E;
    }
}

extern "C" void kernel_launch(void* const* d_in, const int* in_sizes, int n_in,
                              void* d_out, int out_size) {
    const float* pos  = (const float*)d_in[0];
    const float* cell = (const float*)d_in[1];
    const float* q    = (const float*)d_in[2];
    const float* sigt = (const float*)d_in[3];
    const int*   spec = (const int*)d_in[4];
    const int*   nsr  = (const int*)d_in[5];
    const int*   nkr  = (const int*)d_in[6];
    int n = in_sizes[0] / 3;
    int ntypes = in_sizes[3];

    int setupThreads = NT1 + NT2 + MAXT * MAXT + MAXN;
    k_setup<<<(setupThreads + TPB - 1) / TPB, TPB>>>(pos, cell, q, sigt, n, ntypes);

    int nt = (n + TS - 1) / TS;
    int nTilePairs = nt * (nt + 1) / 2;
    unsigned int total = NB_RECIP + nTilePairs;
    k_main<<<total, TPB>>>(pos, cell, q, sigt, spec, nsr, nkr,
                           (float*)d_out, n, ntypes, total);
}

// round 15
// speedup vs baseline: 1.4341x; 1.4341x over previous
#include <cuda_runtime.h>
#include <math.h>

#define TPB 256
#define TS 32
#define MAXA 1024
#define NK_HALF 2456   // half-space of 17^3 grid; 307*8 warps == 2456 exactly
#define NB_RECIP 307
#define FULLMASK 0xffffffffu

struct AccT {
    double r[32];
    double k[32];
    unsigned int cnt;
    unsigned int pad[31];
};
__device__ AccT g_acc;   // zero at load; self-resetting per run

struct SCon {
    float c00, c11, c22;
    float iLx, iLy, iLz;
    float cutr2, inve, eA;        // eA = -log2(e) * inve^2
    float vol, eta, cutk2, id, e2;
    float M[9];                   // 2pi * inv(cell)^T, row-major M[b*3+a]
    int ns, nk, fastf;
};

__device__ __forceinline__ float blockReduceF(float v) {
    __shared__ float sh[32];
    int lane = threadIdx.x & 31, w = threadIdx.x >> 5;
    #pragma unroll
    for (int o = 16; o; o >>= 1) v += __shfl_down_sync(FULLMASK, v, o);
    if (lane == 0) sh[w] = v;
    __syncthreads();
    if (w == 0) {
        v = (lane < (TPB >> 5)) ? sh[lane] : 0.f;
        #pragma unroll
        for (int o = 16; o; o >>= 1) v += __shfl_down_sync(FULLMASK, v, o);
    }
    return v;
}

// AS 7.1.26 polynomial in t = 1/(1+0.3275911 x)
__device__ __forceinline__ float as_poly(float t) {
    return t * fmaf(t, fmaf(t, fmaf(t, fmaf(t, 1.061405429f, -1.453152027f),
           1.421413741f), -0.284496736f), 0.254829592f);
}

// full erfc (slow path only)
__device__ __forceinline__ float erfc_as(float x) {
    float t = __fdividef(1.0f, fmaf(0.3275911f, x, 1.0f));
    return as_poly(t) * __expf(-x * x);
}

__global__ void __launch_bounds__(TPB)
k_main(const float* __restrict__ pos, const float* __restrict__ cell,
       const float* __restrict__ q, const float* __restrict__ sigt,
       const int* __restrict__ spec, const int* __restrict__ nsr,
       const int* __restrict__ nkr, float* __restrict__ out,
       int n, unsigned int total_blocks) {
    __shared__ SCon sc;
    __shared__ union SM {
        float4 at[MAXA];                               // recip: staged atoms
        struct {
            float4 jt[TS]; float4 it[TS];
            float  js2[TS]; float  is2[TS];
        } t;                                           // real: tiles
    } sm;
    int tid = threadIdx.x;
    int b = blockIdx.x;
    bool isRecip = (b < NB_RECIP);

    // tile indices (cheap, needed by staging threads before sync)
    int ti = 0, tj = 0; bool diagT = false;
    if (!isRecip) {
        int bt = b - NB_RECIP;
        ti = (int)(sqrtf(2.0f * (float)bt + 0.25f) - 0.5f);
        if ((ti + 1) * (ti + 2) / 2 <= bt) ++ti;
        if (ti * (ti + 1) / 2 > bt) --ti;
        tj = bt - ti * (ti + 1) / 2;
        diagT = (ti == tj);
    }

    // ---- thread 0: block constants; threads >=32: concurrent staging -------
    if (tid == 0) {
        float c00 = cell[0], c01 = cell[1], c02 = cell[2];
        float c10 = cell[3], c11 = cell[4], c12 = cell[5];
        float c20 = cell[6], c21 = cell[7], c22 = cell[8];
        float det = c00 * (c11*c22 - c12*c21) - c01 * (c10*c22 - c12*c20)
                  + c02 * (c10*c21 - c11*c20);
        float vol = fabsf(det);
        float eta = __expf(__logf(vol * vol / (float)n) * 0.16666667f)
                    * 0.39894228040143267f;
        const float SQRT_2LOG = 6.0697085114f;
        float cutr = SQRT_2LOG * eta;
        float cutr2 = cutr * cutr;
        float inve = 0.7071067811865476f / eta;
        sc.c00 = c00; sc.c11 = c11; sc.c22 = c22;
        sc.iLx = __fdividef(1.0f, c00);
        sc.iLy = __fdividef(1.0f, c11);
        sc.iLz = __fdividef(1.0f, c22);
        sc.cutr2 = cutr2;
        sc.inve = inve;
        sc.eA = -1.4426950408889634f * inve * inve;
        sc.vol = vol; sc.eta = eta;
        float cutk = SQRT_2LOG / eta;
        sc.cutk2 = cutk * cutk;
        float id = __fdividef(6.283185307179586f, det);
        sc.id = id;
        sc.e2 = eta * eta;
        sc.M[0] = (c11*c22 - c12*c21) * id;
        sc.M[1] = (c02*c21 - c01*c22) * id;
        sc.M[2] = (c01*c12 - c02*c11) * id;
        sc.M[3] = (c12*c20 - c10*c22) * id;
        sc.M[4] = (c00*c22 - c02*c20) * id;
        sc.M[5] = (c02*c10 - c00*c12) * id;
        sc.M[6] = (c10*c21 - c11*c20) * id;
        sc.M[7] = (c01*c20 - c00*c21) * id;
        sc.M[8] = (c00*c11 - c01*c10) * id;
        int ns = nsr[0];
        sc.ns = ns;
        sc.nk = nkr[0];
        bool diag = (c01==0.f && c02==0.f && c10==0.f && c12==0.f
                     && c20==0.f && c21==0.f);
        sc.fastf = (diag && ns >= 1 && cutr2 <= c00*c00 && cutr2 <= c11*c11
                    && cutr2 <= c22*c22) ? 1 : 0;
    }
    if (isRecip) {
        if (tid >= 32) {
            int lim = (n < MAXA) ? n : MAXA;
            for (int a = tid - 32; a < lim; a += TPB - 32)
                sm.at[a] = make_float4(__ldg(pos+3*a), __ldg(pos+3*a+1),
                                       __ldg(pos+3*a+2), __ldg(q+a));
        }
    } else {
        if (tid >= 32 && tid < 32 + TS) {       // j-tile (q pre-folded x2 off-diag)
            int jl = tid - 32;
            int a = tj * TS + jl;
            float4 v = make_float4(0.f, 0.f, 0.f, 0.f);
            float s2 = 1.f;
            if (a < n) {
                v = make_float4(__ldg(pos+3*a), __ldg(pos+3*a+1), __ldg(pos+3*a+2),
                                __ldg(q+a) * (diagT ? 1.0f : 2.0f));
                float sg = __ldg(sigt + __ldg(spec + a));
                s2 = 2.0f * sg * sg;
            }
            sm.t.jt[jl] = v; sm.t.js2[jl] = s2;
        } else if (tid >= 32 + TS && tid < 32 + 2 * TS) {   // i-tile
            int il = tid - 32 - TS;
            int a = ti * TS + il;
            float4 v = make_float4(0.f, 0.f, 0.f, 0.f);
            float s2 = 1.f;
            if (a < n) {
                v = make_float4(__ldg(pos+3*a), __ldg(pos+3*a+1), __ldg(pos+3*a+2),
                                __ldg(q+a));
                float sg = __ldg(sigt + __ldg(spec + a));
                s2 = 2.0f * sg * sg;
            }
            sm.t.it[il] = v; sm.t.is2[il] = s2;
        }
    }
    __syncthreads();

    if (isRecip) {
        // ---------- reciprocal: one warp per half-space k --------------------
        int w = tid >> 5, lane = tid & 31;
        int widx = b * 8 + w;
        int f = 2457 + widx;
        int kx = f % 17 - 8;
        int ky = (f / 17) % 17 - 8;
        int kz = f / 289 - 8;
        int nk = sc.nk;
        if (abs(kx) <= nk && abs(ky) <= nk && abs(kz) <= nk) {
            float kax = kx * sc.M[0] + ky * sc.M[3] + kz * sc.M[6];
            float kay = kx * sc.M[1] + ky * sc.M[4] + kz * sc.M[7];
            float kaz = kx * sc.M[2] + ky * sc.M[5] + kz * sc.M[8];
            float k2 = kax*kax + kay*kay + kaz*kaz;
            if (k2 > 1e-16f && k2 < sc.cutk2) {
                const float TWO_PI = 6.283185307179586f;
                float wgt = __fdividef(__expf(-0.5f * sc.e2 * k2), k2);
                float scv = 0.f, ssv = 0.f;
                for (int i2 = lane; i2 < n; i2 += 32) {
                    float4 p = (i2 < MAXA) ? sm.at[i2]
                             : make_float4(__ldg(pos+3*i2), __ldg(pos+3*i2+1),
                                           __ldg(pos+3*i2+2), __ldg(q+i2));
                    float th = fmaf(kax, p.x, fmaf(kay, p.y, kaz * p.z));
                    th -= TWO_PI * rintf(th * 0.15915494309189535f);
                    float s, c;
                    __sincosf(th, &s, &c);
                    scv = fmaf(p.w, c, scv);
                    ssv = fmaf(p.w, s, ssv);
                }
                #pragma unroll
                for (int o = 16; o; o >>= 1) {
                    scv += __shfl_down_sync(FULLMASK, scv, o);
                    ssv += __shfl_down_sync(FULLMASK, ssv, o);
                }
                if (lane == 0)
                    atomicAdd(&g_acc.k[widx & 31],
                              (double)(2.0f * wgt * (scv*scv + ssv*ssv)));
            }
        }
    } else {
        // ---------- real space: 32x32 tile pair, 4 j's per thread ------------
        int li = tid & 31;
        int i = ti * TS + li;
        float4 Pi = sm.t.it[li];
        float s2i = sm.t.is2[li];
        float qi  = Pi.w;
        int jj0 = (tid >> 5) * 4;
        float local = 0.f;
        float cutr2 = sc.cutr2;

        if (sc.fastf) {   // block-uniform
            float c00 = sc.c00, c11 = sc.c11, c22 = sc.c22;
            float iLx = sc.iLx, iLy = sc.iLy, iLz = sc.iLz;
            float inve = sc.inve, eA = sc.eA;
            const float L2E = 1.4426950408889634f;

            #pragma unroll
            for (int u = 0; u < 4; ++u) {
                int jl = jj0 + u;
                float4 Pj = sm.t.jt[jl];
                float s2j = sm.t.js2[jl];
                float qq = qi * Pj.w;
                if (diagT) {
                    int j = tj * TS + jl;
                    qq *= (j < i) ? 2.0f : ((j == i) ? 1.0f : 0.0f);
                }

                float dx = Pj.x - Pi.x, dy = Pj.y - Pi.y, dz = Pj.z - Pi.z;
                float invg  = rsqrtf(s2i + s2j);
                float invg2 = invg * invg;
                float eB = -L2E * invg2;

                float x0 = fmaf(-c00, rintf(dx * iLx), dx);
                float y0 = fmaf(-c11, rintf(dy * iLy), dy);
                float z0 = fmaf(-c22, rintf(dz * iLz), dz);
                float x1 = x0 - copysignf(c00, x0);
                float y1 = y0 - copysignf(c11, y0);
                float z1 = z0 - copysignf(c22, z0);
                float xs0 = x0*x0, xs1 = x1*x1;
                float ys0 = y0*y0, ys1 = y1*y1;
                float zs0 = z0*z0, zs1 = z1*z1;

                // min image: both erfc chains
                {
                    float r2 = xs0 + ys0 + zs0;
                    if (r2 > 1e-16f && r2 < cutr2) {
                        float rinv = rsqrtf(r2);
                        float r = r2 * rinv;
                        float vA = as_poly(__frcp_rn(fmaf(0.3275911f, r * inve, 1.0f)))
                                   * exp2f(r2 * eA);
                        float vB = as_poly(__frcp_rn(fmaf(0.3275911f, r * invg, 1.0f)))
                                   * exp2f(r2 * eB);
                        local = fmaf(qq, (vA - vB) * rinv, local);
                    }
                }
                // secondary images: lane-local mask pop, eta chain + guarded gamma
                unsigned int mask = 0u;
                #pragma unroll
                for (int c = 1; c < 8; ++c) {
                    float r2 = ((c & 1) ? xs1 : xs0) + ((c & 2) ? ys1 : ys0)
                             + ((c & 4) ? zs1 : zs0);
                    mask |= (r2 < cutr2 ? 1u : 0u) << c;
                }
                while (mask) {
                    int c = __ffs(mask) - 1;
                    mask &= mask - 1;
                    float r2 = ((c & 1) ? xs1 : xs0) + ((c & 2) ? ys1 : ys0)
                             + ((c & 4) ? zs1 : zs0);
                    float rinv = rsqrtf(r2);
                    float r = r2 * rinv;
                    float v = as_poly(__frcp_rn(fmaf(0.3275911f, r * inve, 1.0f)))
                              * exp2f(r2 * eA);
                    if (r2 * invg2 < 16.5f)   // gamma non-negligible (~never: r>=L/2)
                        v -= as_poly(__frcp_rn(fmaf(0.3275911f, r * invg, 1.0f)))
                             * exp2f(r2 * eB);
                    local = fmaf(qq, v * rinv, local);
                }
            }
        } else {
            float c00 = __ldg(cell+0), c01 = __ldg(cell+1), c02 = __ldg(cell+2);
            float c10 = __ldg(cell+3), c11 = __ldg(cell+4), c12 = __ldg(cell+5);
            float c20 = __ldg(cell+6), c21 = __ldg(cell+7), c22 = __ldg(cell+8);
            float inve = sc.inve;
            int ns = sc.ns;
            #pragma unroll 1
            for (int u = 0; u < 4; ++u) {
                int jl = jj0 + u;
                int j = tj * TS + jl;
                float4 Pj = sm.t.jt[jl];
                float s2j = sm.t.js2[jl];
                float qq = qi * Pj.w;
                if (diagT) qq *= (j < i) ? 2.0f : ((j == i) ? 1.0f : 0.0f);
                float dx = Pj.x - Pi.x, dy = Pj.y - Pi.y, dz = Pj.z - Pi.z;
                float invg = rsqrtf(s2i + s2j);

                for (int sx = -ns; sx <= ns; ++sx)
                    for (int sy = -ns; sy <= ns; ++sy) {
                        float bx = dx + sx*c00 + sy*c10;
                        float by = dy + sx*c01 + sy*c11;
                        float bz = dz + sx*c02 + sy*c12;
                        for (int sz = -ns; sz <= ns; ++sz) {
                            float ax = bx + sz*c20, ay = by + sz*c21, az = bz + sz*c22;
                            float r2 = ax*ax + ay*ay + az*az;
                            if (r2 > 1e-16f && r2 < cutr2) {
                                float rinv = rsqrtf(r2);
                                float r = r2 * rinv;
                                local += qq * (erfc_as(r*inve) - erfc_as(r*invg)) * rinv;
                            }
                        }
                    }
            }
        }
        float tot = blockReduceF(local);
        if (tid == 0) atomicAdd(&g_acc.r[b & 31], (double)tot);
    }

    // ---------------- last block: self term + combine + RESET ---------------
    __shared__ bool isLast;
    __syncthreads();
    if (tid == 0) {
        __threadfence();
        unsigned int prev = atomicAdd(&g_acc.cnt, 1u);
        isLast = (prev == total_blocks - 1);
    }
    __syncthreads();
    if (!isLast) return;

    __shared__ double shd[64];
    if (tid < 64)
        shd[tid] = (tid < 32) ? __ldcg(&g_acc.r[tid]) : __ldcg(&g_acc.k[tid - 32]);
    __syncthreads();

    if (tid < 32) { g_acc.r[tid] = 0.0; g_acc.k[tid] = 0.0; }
    if (tid == 0) g_acc.cnt = 0u;

    float a = -0.7978845608028654f / sc.eta;
    float selfLocal = 0.f;
    for (int i2 = tid; i2 < n; i2 += TPB) {
        float qv = __ldg(q + i2);
        float sg = __ldg(sigt + __ldg(spec + i2));
        selfLocal += qv * qv * (a + 0.5641895835477563f / sg);
    }
    float selfSum = blockReduceF(selfLocal);
    if (tid == 0) {
        double sr = 0.0, sk = 0.0;
        #pragma unroll
        for (int tt = 0; tt < 32; ++tt) { sr += shd[tt]; sk += shd[32 + tt]; }
        const double COEF = 14.399645478425668;
        double E = 0.5 * COEF * (sr + (4.0 * M_PI / (double)sc.vol) * sk
                                 + (double)selfSum);
        out[0] = (float)E;
    }
}

extern "C" void kernel_launch(void* const* d_in, const int* in_sizes, int n_in,
                              void* d_out, int out_size) {
    const float* pos  = (const float*)d_in[0];
    const float* cell = (const float*)d_in[1];
    const float* q    = (const float*)d_in[2];
    const float* sigt = (const float*)d_in[3];
    const int*   spec = (const int*)d_in[4];
    const int*   nsr  = (const int*)d_in[5];
    const int*   nkr  = (const int*)d_in[6];
    int n = in_sizes[0] / 3;

    int nt = (n + TS - 1) / TS;
    int nTilePairs = nt * (nt + 1) / 2;
    unsigned int total = NB_RECIP + nTilePairs;
    k_main<<<total, TPB>>>(pos, cell, q, sigt, spec, nsr, nkr,
                           (float*)d_out, n, total);
}